// round 14
// baseline (speedup 1.0000x reference)
#include <cuda_runtime.h>
#include <math.h>

#define BB 2
#define CC 32
#define EE 128
#define SS 64
#define VV (SS*SS*SS)       /* 262144 = 2^18 */
#define KV 343
#define NTOT (BB*VV)        /* compact-array capacity/stride: 524288 */

typedef unsigned long long ull;

/* ---- scratch (static __device__: allocation-free per harness rules) ---- */
__device__ float    g_yc[(size_t)CC*NTOT]; /* conv out, compact channel-major [c][slot] */
__device__ float    g_o [(size_t)CC*NTOT]; /* mlp  out, compact channel-major [c][slot] */
__device__ int      g_rank[NTOT];          /* voxel -> slot (-1 inactive) */
__device__ unsigned g_bits[NTOT/32];       /* active-mask bitfield, bit v&31 of word v>>5 */
__device__ int      g_cnt;

/* ---------------- K0: reset counter ---------------- */
__global__ void k0_reset() { if (threadIdx.x == 0) g_cnt = 0; }

/* ---------------- K1: build rank + bitmask (reads ONLY mask: ~2MB) ------------- */
__global__ __launch_bounds__(256) void k1_rank_bits(const int* __restrict__ mask)
{
    int t  = blockIdx.x * blockDim.x + threadIdx.x;   /* t in [0, B*V/4) */
    int i0 = t * 4;
    int4 m4 = *(const int4*)(mask + i0);

    int lane = threadIdx.x & 31;
    int a0 = (m4.x != 0), a1 = (m4.y != 0), a2 = (m4.z != 0), a3 = (m4.w != 0);
    int cnt4 = a0 + a1 + a2 + a3;
    int incl = cnt4;
#pragma unroll
    for (int d = 1; d < 32; d <<= 1) {
        int p = __shfl_up_sync(0xffffffffu, incl, d);
        if (lane >= d) incl += p;
    }
    int excl  = incl - cnt4;
    int total = __shfl_sync(0xffffffffu, incl, 31);
    int base  = 0;
    if (lane == 31) base = atomicAdd(&g_cnt, total);
    base = __shfl_sync(0xffffffffu, base, 31);

    int r = base + excl;
    int4 rk;
    rk.x = a0 ? r : -1; r += a0;
    rk.y = a1 ? r : -1; r += a1;
    rk.z = a2 ? r : -1; r += a2;
    rk.w = a3 ? r : -1;
    *(int4*)(g_rank + i0) = rk;

    /* bitmask: 8 lanes (one 32-voxel word) OR their nibbles via shfl_xor */
    unsigned nib = (unsigned)(a0 | (a1 << 1) | (a2 << 2) | (a3 << 3)) << ((lane & 7) * 4);
    nib |= __shfl_xor_sync(0xffffffffu, nib, 1);
    nib |= __shfl_xor_sync(0xffffffffu, nib, 2);
    nib |= __shfl_xor_sync(0xffffffffu, nib, 4);
    if ((lane & 7) == 0) g_bits[i0 >> 5] = nib;
}

/* ---------------- K2: depthwise 7x7x7 conv, f32x2, SINGLE-copy smem ------------
 * Compute identical to passing R8/R12 core; tile load now reads X directly and
 * applies the active-bit (from g_bits) on the fly -> k1 no longer writes xm. */
#define K2_XP 40
#define K2_YW 14
#define K2_ZW 14
#define K2_XW 38
#define K2_TILE (K2_ZW * K2_YW * K2_XP)   /* 7840 floats */

__device__ __forceinline__ ull ffma2(ull a, ull b, ull c) {
    ull d;
    asm("fma.rn.f32x2 %0, %1, %2, %3;" : "=l"(d) : "l"(a), "l"(b), "l"(c));
    return d;
}
__device__ __forceinline__ ull pack2(float lo, float hi) {
    ull r;
    asm("mov.b64 %0, {%1, %2};" : "=l"(r) : "f"(lo), "f"(hi));
    return r;
}
__device__ __forceinline__ void unpack2(ull v, float& lo, float& hi) {
    asm("mov.b64 {%0, %1}, %2;" : "=f"(lo), "=f"(hi) : "l"(v));
}

__global__ __launch_bounds__(128) void k2_dwconv(
    const float* __restrict__ x,
    const float* __restrict__ w_dw,
    const float* __restrict__ b_dw)
{
    __shared__ __align__(16) float  s_in[K2_TILE];
    __shared__ __align__(16) float2 wdup[KV];

    int c = blockIdx.y, b = blockIdx.z;
    int t  = blockIdx.x;               /* 128 tiles: 2x * 8y * 8z */
    int xt = t & 1;
    int yt = (t >> 1) & 7;
    int zt = t >> 4;
    int x0 = xt * 32, y0 = yt * 8, z0 = zt * 8;
    int tid = threadIdx.x;

    const float* wsrc = w_dw + c * KV;
    for (int j = tid; j < KV; j += 128) {
        float w = wsrc[j];
        wdup[j] = make_float2(w, w);
    }

    const float*    src = x + (size_t)(b * CC + c) * VV;
    const unsigned* bts = g_bits + (b << 13);          /* VV/32 = 8192 words */
    for (int j = tid; j < K2_ZW * K2_YW * K2_XW; j += 128) {
        int lz = j / (K2_YW * K2_XW);
        int r  = j - lz * (K2_YW * K2_XW);
        int ly = r / K2_XW;
        int lx = r - ly * K2_XW;
        int gz = z0 - 3 + lz, gy = y0 - 3 + ly, gx = x0 - 3 + lx;
        float val = 0.f;
        if (((unsigned)gz < SS) & ((unsigned)gy < SS) & ((unsigned)gx < SS)) {
            int v = gz * 4096 + gy * 64 + gx;
            unsigned w = bts[v >> 5];
            val = ((w >> (v & 31)) & 1u) ? src[v] : 0.f;
        }
        s_in[(lz * K2_YW + ly) * K2_XP + lx] = val;
    }
    __syncthreads();

    int xp = tid & 15;
    int ty = tid >> 4;

    ull acc[8];
#pragma unroll
    for (int k = 0; k < 8; k++) acc[k] = 0ULL;

#pragma unroll 1
    for (int dy = 0; dy < 7; dy++) {
        const float* row = s_in + (ty + dy) * K2_XP + 2 * xp;
        float hi[K2_ZW];

        {
            ull wz[7];
#pragma unroll
            for (int dz = 0; dz < 7; dz++)
                wz[dz] = *(const ull*)&wdup[(dz * 7 + dy) * 7 + 0];
#pragma unroll
            for (int j = 0; j < K2_ZW; j++) {
                float2 wv = *(const float2*)(row + j * (K2_YW * K2_XP));
                ull v = pack2(wv.x, wv.y);
#pragma unroll
                for (int dz = 0; dz < 7; dz++) {
                    int k = j - dz;
                    if (k >= 0 && k < 8) acc[k] = ffma2(wz[dz], v, acc[k]);
                }
                hi[j] = wv.y;
            }
        }

#pragma unroll
        for (int e = 2; e <= 6; e += 2) {
            ull wzo[7], wze[7];
#pragma unroll
            for (int dz = 0; dz < 7; dz++) {
                wzo[dz] = *(const ull*)&wdup[(dz * 7 + dy) * 7 + (e - 1)];
                wze[dz] = *(const ull*)&wdup[(dz * 7 + dy) * 7 + e];
            }
#pragma unroll
            for (int j = 0; j < K2_ZW; j++) {
                float2 wv = *(const float2*)(row + j * (K2_YW * K2_XP) + e);
                ull q = pack2(hi[j], wv.x);
                ull v = pack2(wv.x, wv.y);
#pragma unroll
                for (int dz = 0; dz < 7; dz++) {
                    int k = j - dz;
                    if (k >= 0 && k < 8) {
                        acc[k] = ffma2(wzo[dz], q, acc[k]);
                        acc[k] = ffma2(wze[dz], v, acc[k]);
                    }
                }
                hi[j] = wv.y;
            }
        }
    }

    float bd = b_dw[c];
    int gx = x0 + 2 * xp, gy = y0 + ty;
    const int* rkp = g_rank + b * VV;
    float*     dst = g_yc + (size_t)c * NTOT;
#pragma unroll
    for (int k = 0; k < 8; k++) {
        int v = (z0 + k) * 4096 + gy * 64 + gx;
        int2 rr = *(const int2*)(rkp + v);           /* gx even -> 8B aligned */
        float lo = __uint_as_float((unsigned)acc[k]);
        float hi2 = __uint_as_float((unsigned)(acc[k] >> 32));
        if (rr.x >= 0) dst[rr.x] = lo + bd;
        if (rr.y >= 0) dst[rr.y] = hi2 + bd;
    }
}

/* ---------------- K3: LN + expand/GELU + project, 2 SLOTS per thread -----------
 * Weight LDS.64 is warp-uniform broadcast (the binding resource per R12 ncu:
 * L1=80.7%); sharing each loaded weight across two slots halves total LDS
 * wavefronts. Block covers 256 slots (tid -> s0, s0+128). */
__device__ __forceinline__ float gelu_f(float x) {
    return 0.5f * x * (1.f + erff(x * 0.70710678118654752440f));
}

__global__ __launch_bounds__(128, 3) void k3_mlp(
    const float* __restrict__ ln_g, const float* __restrict__ ln_b,
    const float* __restrict__ w2,   const float* __restrict__ b2,
    const float* __restrict__ w3,   const float* __restrict__ b3)
{
    int n = g_cnt;
    int base = blockIdx.x * 256;
    if (base >= n) return;

    __shared__ __align__(16) float w2s[EE * CC];   /* [E][C] as-is */
    __shared__ __align__(16) float w3t[EE * CC];   /* transposed: [e][c] */
    __shared__ __align__(16) float b2s[EE];
    __shared__ __align__(16) float prm[3 * CC];    /* ln_g | ln_b | b3 */

    int tid = threadIdx.x;
    for (int j = tid; j < EE * CC; j += 128) {
        w2s[j] = w2[j];
        int e = j >> 5, cI = j & 31;
        w3t[j] = w3[cI * EE + e];
    }
    b2s[tid] = b2[tid];
    if (tid < CC) { prm[tid] = ln_g[tid]; prm[CC + tid] = ln_b[tid]; prm[2 * CC + tid] = b3[tid]; }
    __syncthreads();

    int  s0 = base + tid, s1 = s0 + 128;
    bool ok0 = s0 < n, ok1 = s1 < n;
    int  sl0 = ok0 ? s0 : (n - 1);
    int  sl1 = ok1 ? s1 : (n - 1);

    ull yA[CC / 2], yB[CC / 2];
    {
        float yv[CC];
#pragma unroll
        for (int c = 0; c < CC; c++) yv[c] = g_yc[(size_t)c * NTOT + sl0];
        float sm = 0.f;
#pragma unroll
        for (int c = 0; c < CC; c++) sm += yv[c];
        float mu = sm * (1.f / CC);
        float vs = 0.f;
#pragma unroll
        for (int c = 0; c < CC; c++) { float d = yv[c] - mu; vs = fmaf(d, d, vs); }
        float rs = rsqrtf(vs * (1.f / CC) + 1e-6f);
#pragma unroll
        for (int q = 0; q < CC / 2; q++) {
            float a0 = fmaf((yv[2*q]   - mu) * rs, prm[2*q],   prm[CC + 2*q]);
            float a1 = fmaf((yv[2*q+1] - mu) * rs, prm[2*q+1], prm[CC + 2*q+1]);
            yA[q] = pack2(a0, a1);
        }
    }
    {
        float yv[CC];
#pragma unroll
        for (int c = 0; c < CC; c++) yv[c] = g_yc[(size_t)c * NTOT + sl1];
        float sm = 0.f;
#pragma unroll
        for (int c = 0; c < CC; c++) sm += yv[c];
        float mu = sm * (1.f / CC);
        float vs = 0.f;
#pragma unroll
        for (int c = 0; c < CC; c++) { float d = yv[c] - mu; vs = fmaf(d, d, vs); }
        float rs = rsqrtf(vs * (1.f / CC) + 1e-6f);
#pragma unroll
        for (int q = 0; q < CC / 2; q++) {
            float a0 = fmaf((yv[2*q]   - mu) * rs, prm[2*q],   prm[CC + 2*q]);
            float a1 = fmaf((yv[2*q+1] - mu) * rs, prm[2*q+1], prm[CC + 2*q+1]);
            yB[q] = pack2(a0, a1);
        }
    }

    ull oA[CC / 2], oB[CC / 2];
#pragma unroll
    for (int q = 0; q < CC / 2; q++) {
        ull b3p = *(const ull*)&prm[2 * CC + 2 * q];
        oA[q] = b3p;
        oB[q] = b3p;
    }

    const ull* w2v = (const ull*)w2s;
    const ull* w3v = (const ull*)w3t;

#pragma unroll 1
    for (int e = 0; e < EE; e++) {
        ull zA = 0ULL, zB = 0ULL;
#pragma unroll
        for (int q = 0; q < CC / 2; q++) {
            ull w = w2v[e * (CC / 2) + q];          /* one broadcast LDS, two slots */
            zA = ffma2(yA[q], w, zA);
            zB = ffma2(yB[q], w, zB);
        }
        float la, ha, lb, hb;
        unpack2(zA, la, ha);
        unpack2(zB, lb, hb);
        float be = b2s[e];
        float hAs = gelu_f(be + la + ha);
        float hBs = gelu_f(be + lb + hb);
        ull hA = pack2(hAs, hAs);
        ull hB = pack2(hBs, hBs);
#pragma unroll
        for (int q = 0; q < CC / 2; q++) {
            ull w = w3v[e * (CC / 2) + q];          /* one broadcast LDS, two slots */
            oA[q] = ffma2(hA, w, oA[q]);
            oB[q] = ffma2(hB, w, oB[q]);
        }
    }

    if (ok0) {
#pragma unroll
        for (int q = 0; q < CC / 2; q++) {
            float lo, hi;
            unpack2(oA[q], lo, hi);
            g_o[(size_t)(2*q)   * NTOT + s0] = lo;
            g_o[(size_t)(2*q+1) * NTOT + s0] = hi;
        }
    }
    if (ok1) {
#pragma unroll
        for (int q = 0; q < CC / 2; q++) {
            float lo, hi;
            unpack2(oB[q], lo, hi);
            g_o[(size_t)(2*q)   * NTOT + s1] = lo;
            g_o[(size_t)(2*q+1) * NTOT + s1] = hi;
        }
    }
}

/* ---------------- K4: out = x*m + o  (never READS out) -------------------------
 * One thread = 4 consecutive voxels; writes all of out (poisoned by harness).
 * Active: out = x + o[rank]; inactive: out = 0. */
__global__ __launch_bounds__(256) void k4_residual(
    const float* __restrict__ x, float* __restrict__ out)
{
    int t  = blockIdx.x * blockDim.x + threadIdx.x;
    int i0 = t * 4;
    int b  = i0 >> 18;
    int v  = i0 & (VV - 1);
    int4 rk = *(const int4*)(g_rank + i0);

    float* ob = out + (size_t)b * CC * VV + v;
    if ((rk.x < 0) & (rk.y < 0) & (rk.z < 0) & (rk.w < 0)) {
        float4 z = make_float4(0.f, 0.f, 0.f, 0.f);
#pragma unroll
        for (int c = 0; c < CC; c++)
            *(float4*)(ob + (size_t)c * VV) = z;
        return;
    }

    const float* xb = x + (size_t)b * CC * VV + v;
#pragma unroll
    for (int c = 0; c < CC; c++) {
        const float* oc = g_o + (size_t)c * NTOT;
        float4 xv = *(const float4*)(xb + (size_t)c * VV);
        float4 ov;
        ov.x = (rk.x >= 0) ? xv.x + oc[rk.x] : 0.f;
        ov.y = (rk.y >= 0) ? xv.y + oc[rk.y] : 0.f;
        ov.z = (rk.z >= 0) ? xv.z + oc[rk.z] : 0.f;
        ov.w = (rk.w >= 0) ? xv.w + oc[rk.w] : 0.f;
        *(float4*)(ob + (size_t)c * VV) = ov;
    }
}

/* ---------------- launcher ---------------- */
extern "C" void kernel_launch(void* const* d_in, const int* in_sizes, int n_in,
                              void* d_out, int out_size)
{
    const float* x    = (const float*)d_in[0];
    const int*   mask = (const int*)  d_in[1];
    const float* w_dw = (const float*)d_in[2];
    const float* b_dw = (const float*)d_in[3];
    const float* ln_g = (const float*)d_in[4];
    const float* ln_b = (const float*)d_in[5];
    const float* w2   = (const float*)d_in[6];
    const float* b2   = (const float*)d_in[7];
    const float* w3   = (const float*)d_in[8];
    const float* b3   = (const float*)d_in[9];
    float* out = (float*)d_out;

    k0_reset<<<1, 32>>>();
    k1_rank_bits<<<(BB * VV / 4) / 256, 256>>>(mask);
    dim3 g2(128, CC, BB);
    k2_dwconv<<<g2, 128>>>(x, w_dw, b_dw);
    k3_mlp<<<NTOT / 256, 128>>>(ln_g, ln_b, w2, b2, w3, b3);
    k4_residual<<<(BB * VV / 4) / 256, 256>>>(x, out);
}

// round 17
// speedup vs baseline: 1.0930x; 1.0930x over previous
#include <cuda_runtime.h>
#include <math.h>

#define BB 2
#define CC 32
#define EE 128
#define SS 64
#define VV (SS*SS*SS)       /* 262144 = 2^18 */
#define KV 343
#define NTOT (BB*VV)        /* compact-array capacity/stride: 524288 */

typedef unsigned long long ull;

/* ---- scratch (static __device__: allocation-free per harness rules) ---- */
__device__ float    g_yc[(size_t)CC*NTOT]; /* conv out, compact channel-major [c][slot] */
__device__ float    g_o [(size_t)CC*NTOT]; /* mlp  out, compact channel-major [c][slot] */
__device__ int      g_rank[NTOT];          /* voxel -> slot (-1 inactive) */
__device__ unsigned g_bits[NTOT/32];       /* active-mask bitfield, bit v&31 of word v>>5 */
__device__ int      g_cnt;

/* ---------------- K0: reset counter ---------------- */
__global__ void k0_reset() { if (threadIdx.x == 0) g_cnt = 0; }

/* ---------------- K1: build rank + bitmask (reads ONLY mask: ~2MB) ------------- */
__global__ __launch_bounds__(256) void k1_rank_bits(const int* __restrict__ mask)
{
    int t  = blockIdx.x * blockDim.x + threadIdx.x;   /* t in [0, B*V/4) */
    int i0 = t * 4;
    int4 m4 = *(const int4*)(mask + i0);

    int lane = threadIdx.x & 31;
    int a0 = (m4.x != 0), a1 = (m4.y != 0), a2 = (m4.z != 0), a3 = (m4.w != 0);
    int cnt4 = a0 + a1 + a2 + a3;
    int incl = cnt4;
#pragma unroll
    for (int d = 1; d < 32; d <<= 1) {
        int p = __shfl_up_sync(0xffffffffu, incl, d);
        if (lane >= d) incl += p;
    }
    int excl  = incl - cnt4;
    int total = __shfl_sync(0xffffffffu, incl, 31);
    int base  = 0;
    if (lane == 31) base = atomicAdd(&g_cnt, total);
    base = __shfl_sync(0xffffffffu, base, 31);

    int r = base + excl;
    int4 rk;
    rk.x = a0 ? r : -1; r += a0;
    rk.y = a1 ? r : -1; r += a1;
    rk.z = a2 ? r : -1; r += a2;
    rk.w = a3 ? r : -1;
    *(int4*)(g_rank + i0) = rk;

    /* bitmask: 8 lanes (one 32-voxel word) OR their nibbles via shfl_xor */
    unsigned nib = (unsigned)(a0 | (a1 << 1) | (a2 << 2) | (a3 << 3)) << ((lane & 7) * 4);
    nib |= __shfl_xor_sync(0xffffffffu, nib, 1);
    nib |= __shfl_xor_sync(0xffffffffu, nib, 2);
    nib |= __shfl_xor_sync(0xffffffffu, nib, 4);
    if ((lane & 7) == 0) g_bits[i0 >> 5] = nib;
}

/* ---------------- K2: depthwise 7x7x7 conv, f32x2, SINGLE-copy smem ------------
 * Compute core identical to the proven R8/R12 version (~275us).
 * Tile load reads X directly; active-mask bits STAGED INTO SMEM first so the
 * per-element gate is a cheap LDS (no dependent LDG chain -- the R13 mistake).
 * FIX vs R15: stage THREE bit-words per tile row (the x-halo of odd x-tiles
 * reaches the word left of x0>>5; 2-word staging indexed s_bits[-1]). */
#define K2_XP 40
#define K2_YW 14
#define K2_ZW 14
#define K2_XW 38
#define K2_TILE (K2_ZW * K2_YW * K2_XP)   /* 7840 floats */
#define K2_NBW (K2_ZW * K2_YW * 3)        /* 588 bit-words staged */

__device__ __forceinline__ ull ffma2(ull a, ull b, ull c) {
    ull d;
    asm("fma.rn.f32x2 %0, %1, %2, %3;" : "=l"(d) : "l"(a), "l"(b), "l"(c));
    return d;
}
__device__ __forceinline__ ull pack2(float lo, float hi) {
    ull r;
    asm("mov.b64 %0, {%1, %2};" : "=l"(r) : "f"(lo), "f"(hi));
    return r;
}
__device__ __forceinline__ void unpack2(ull v, float& lo, float& hi) {
    asm("mov.b64 {%0, %1}, %2;" : "=f"(lo), "=f"(hi) : "l"(v));
}

__global__ __launch_bounds__(128) void k2_dwconv(
    const float* __restrict__ x,
    const float* __restrict__ w_dw,
    const float* __restrict__ b_dw)
{
    __shared__ __align__(16) float    s_in[K2_TILE];
    __shared__ __align__(16) float2   wdup[KV];
    __shared__ __align__(16) unsigned s_bits[K2_NBW];

    int c = blockIdx.y, b = blockIdx.z;
    int t  = blockIdx.x;               /* 128 tiles: 2x * 8y * 8z */
    int xt = t & 1;
    int yt = (t >> 1) & 7;
    int zt = t >> 4;
    int x0 = xt * 32, y0 = yt * 8, z0 = zt * 8;
    int tid = threadIdx.x;

    const float* wsrc = w_dw + c * KV;
    for (int j = tid; j < KV; j += 128) {
        float w = wsrc[j];
        wdup[j] = make_float2(w, w);
    }

    /* stage active-bits: per (lz,ly) row, words (x0>>5)-1 .. (x0>>5)+1, clamped */
    const unsigned* bts = g_bits + (b << 13);          /* VV/32 = 8192 words */
    for (int j = tid; j < K2_NBW; j += 128) {
        int lz = j / (K2_YW * 3);
        int r  = j - lz * (K2_YW * 3);
        int ly = r / 3;
        int w  = r - ly * 3;
        int gz = z0 - 3 + lz, gy = y0 - 3 + ly;
        int widx = (x0 >> 5) - 1 + w;
        unsigned bw = 0u;
        if (((unsigned)gz < SS) & ((unsigned)gy < SS) & ((unsigned)widx < 2u))
            bw = bts[gz * 128 + gy * 2 + widx];
        s_bits[j] = bw;
    }
    __syncthreads();

    const float* src = x + (size_t)(b * CC + c) * VV;
    for (int j = tid; j < K2_ZW * K2_YW * K2_XW; j += 128) {
        int lz = j / (K2_YW * K2_XW);
        int r  = j - lz * (K2_YW * K2_XW);
        int ly = r / K2_XW;
        int lx = r - ly * K2_XW;
        int gz = z0 - 3 + lz, gy = y0 - 3 + ly, gx = x0 - 3 + lx;
        float val = 0.f;
        if (((unsigned)gz < SS) & ((unsigned)gy < SS) & ((unsigned)gx < SS)) {
            int off = (int)((unsigned)gx >> 5) - (x0 >> 5) + 1;   /* 0..2 */
            unsigned bw = s_bits[(lz * K2_YW + ly) * 3 + off];
            if ((bw >> (gx & 31)) & 1u)
                val = src[gz * 4096 + gy * 64 + gx];
        }
        s_in[(lz * K2_YW + ly) * K2_XP + lx] = val;
    }
    __syncthreads();

    int xp = tid & 15;
    int ty = tid >> 4;

    ull acc[8];
#pragma unroll
    for (int k = 0; k < 8; k++) acc[k] = 0ULL;

#pragma unroll 1
    for (int dy = 0; dy < 7; dy++) {
        const float* row = s_in + (ty + dy) * K2_XP + 2 * xp;
        float hi[K2_ZW];

        {
            ull wz[7];
#pragma unroll
            for (int dz = 0; dz < 7; dz++)
                wz[dz] = *(const ull*)&wdup[(dz * 7 + dy) * 7 + 0];
#pragma unroll
            for (int j = 0; j < K2_ZW; j++) {
                float2 wv = *(const float2*)(row + j * (K2_YW * K2_XP));
                ull v = pack2(wv.x, wv.y);
#pragma unroll
                for (int dz = 0; dz < 7; dz++) {
                    int k = j - dz;
                    if (k >= 0 && k < 8) acc[k] = ffma2(wz[dz], v, acc[k]);
                }
                hi[j] = wv.y;
            }
        }

#pragma unroll
        for (int e = 2; e <= 6; e += 2) {
            ull wzo[7], wze[7];
#pragma unroll
            for (int dz = 0; dz < 7; dz++) {
                wzo[dz] = *(const ull*)&wdup[(dz * 7 + dy) * 7 + (e - 1)];
                wze[dz] = *(const ull*)&wdup[(dz * 7 + dy) * 7 + e];
            }
#pragma unroll
            for (int j = 0; j < K2_ZW; j++) {
                float2 wv = *(const float2*)(row + j * (K2_YW * K2_XP) + e);
                ull q = pack2(hi[j], wv.x);
                ull v = pack2(wv.x, wv.y);
#pragma unroll
                for (int dz = 0; dz < 7; dz++) {
                    int k = j - dz;
                    if (k >= 0 && k < 8) {
                        acc[k] = ffma2(wzo[dz], q, acc[k]);
                        acc[k] = ffma2(wze[dz], v, acc[k]);
                    }
                }
                hi[j] = wv.y;
            }
        }
    }

    float bd = b_dw[c];
    int gx = x0 + 2 * xp, gy = y0 + ty;
    const int* rkp = g_rank + b * VV;
    float*     dst = g_yc + (size_t)c * NTOT;
#pragma unroll
    for (int k = 0; k < 8; k++) {
        int v = (z0 + k) * 4096 + gy * 64 + gx;
        int2 rr = *(const int2*)(rkp + v);           /* gx even -> 8B aligned */
        float lo = __uint_as_float((unsigned)acc[k]);
        float hi2 = __uint_as_float((unsigned)(acc[k] >> 32));
        if (rr.x >= 0) dst[rr.x] = lo + bd;
        if (rr.y >= 0) dst[rr.y] = hi2 + bd;
    }
}

/* ---------------- K3: LN + expand/GELU + project, 2 SLOTS per thread -----------
 * UNCHANGED from measured 102.6us version: weight LDS.64 broadcast shared
 * across two slots -> halved LDS wavefronts. */
__device__ __forceinline__ float gelu_f(float x) {
    return 0.5f * x * (1.f + erff(x * 0.70710678118654752440f));
}

__global__ __launch_bounds__(128, 3) void k3_mlp(
    const float* __restrict__ ln_g, const float* __restrict__ ln_b,
    const float* __restrict__ w2,   const float* __restrict__ b2,
    const float* __restrict__ w3,   const float* __restrict__ b3)
{
    int n = g_cnt;
    int base = blockIdx.x * 256;
    if (base >= n) return;

    __shared__ __align__(16) float w2s[EE * CC];   /* [E][C] as-is */
    __shared__ __align__(16) float w3t[EE * CC];   /* transposed: [e][c] */
    __shared__ __align__(16) float b2s[EE];
    __shared__ __align__(16) float prm[3 * CC];    /* ln_g | ln_b | b3 */

    int tid = threadIdx.x;
    for (int j = tid; j < EE * CC; j += 128) {
        w2s[j] = w2[j];
        int e = j >> 5, cI = j & 31;
        w3t[j] = w3[cI * EE + e];
    }
    b2s[tid] = b2[tid];
    if (tid < CC) { prm[tid] = ln_g[tid]; prm[CC + tid] = ln_b[tid]; prm[2 * CC + tid] = b3[tid]; }
    __syncthreads();

    int  s0 = base + tid, s1 = s0 + 128;
    bool ok0 = s0 < n, ok1 = s1 < n;
    int  sl0 = ok0 ? s0 : (n - 1);
    int  sl1 = ok1 ? s1 : (n - 1);

    ull yA[CC / 2], yB[CC / 2];
    {
        float yv[CC];
#pragma unroll
        for (int c = 0; c < CC; c++) yv[c] = g_yc[(size_t)c * NTOT + sl0];
        float sm = 0.f;
#pragma unroll
        for (int c = 0; c < CC; c++) sm += yv[c];
        float mu = sm * (1.f / CC);
        float vs = 0.f;
#pragma unroll
        for (int c = 0; c < CC; c++) { float d = yv[c] - mu; vs = fmaf(d, d, vs); }
        float rs = rsqrtf(vs * (1.f / CC) + 1e-6f);
#pragma unroll
        for (int q = 0; q < CC / 2; q++) {
            float a0 = fmaf((yv[2*q]   - mu) * rs, prm[2*q],   prm[CC + 2*q]);
            float a1 = fmaf((yv[2*q+1] - mu) * rs, prm[2*q+1], prm[CC + 2*q+1]);
            yA[q] = pack2(a0, a1);
        }
    }
    {
        float yv[CC];
#pragma unroll
        for (int c = 0; c < CC; c++) yv[c] = g_yc[(size_t)c * NTOT + sl1];
        float sm = 0.f;
#pragma unroll
        for (int c = 0; c < CC; c++) sm += yv[c];
        float mu = sm * (1.f / CC);
        float vs = 0.f;
#pragma unroll
        for (int c = 0; c < CC; c++) { float d = yv[c] - mu; vs = fmaf(d, d, vs); }
        float rs = rsqrtf(vs * (1.f / CC) + 1e-6f);
#pragma unroll
        for (int q = 0; q < CC / 2; q++) {
            float a0 = fmaf((yv[2*q]   - mu) * rs, prm[2*q],   prm[CC + 2*q]);
            float a1 = fmaf((yv[2*q+1] - mu) * rs, prm[2*q+1], prm[CC + 2*q+1]);
            yB[q] = pack2(a0, a1);
        }
    }

    ull oA[CC / 2], oB[CC / 2];
#pragma unroll
    for (int q = 0; q < CC / 2; q++) {
        ull b3p = *(const ull*)&prm[2 * CC + 2 * q];
        oA[q] = b3p;
        oB[q] = b3p;
    }

    const ull* w2v = (const ull*)w2s;
    const ull* w3v = (const ull*)w3t;

#pragma unroll 1
    for (int e = 0; e < EE; e++) {
        ull zA = 0ULL, zB = 0ULL;
#pragma unroll
        for (int q = 0; q < CC / 2; q++) {
            ull w = w2v[e * (CC / 2) + q];          /* one broadcast LDS, two slots */
            zA = ffma2(yA[q], w, zA);
            zB = ffma2(yB[q], w, zB);
        }
        float la, ha, lb, hb;
        unpack2(zA, la, ha);
        unpack2(zB, lb, hb);
        float be = b2s[e];
        float hAs = gelu_f(be + la + ha);
        float hBs = gelu_f(be + lb + hb);
        ull hA = pack2(hAs, hAs);
        ull hB = pack2(hBs, hBs);
#pragma unroll
        for (int q = 0; q < CC / 2; q++) {
            ull w = w3v[e * (CC / 2) + q];          /* one broadcast LDS, two slots */
            oA[q] = ffma2(hA, w, oA[q]);
            oB[q] = ffma2(hB, w, oB[q]);
        }
    }

    if (ok0) {
#pragma unroll
        for (int q = 0; q < CC / 2; q++) {
            float lo, hi;
            unpack2(oA[q], lo, hi);
            g_o[(size_t)(2*q)   * NTOT + s0] = lo;
            g_o[(size_t)(2*q+1) * NTOT + s0] = hi;
        }
    }
    if (ok1) {
#pragma unroll
        for (int q = 0; q < CC / 2; q++) {
            float lo, hi;
            unpack2(oB[q], lo, hi);
            g_o[(size_t)(2*q)   * NTOT + s1] = lo;
            g_o[(size_t)(2*q+1) * NTOT + s1] = hi;
        }
    }
}

/* ---------------- K4: out = x*m + o  (never READS out) ------------------------- */
__global__ __launch_bounds__(256) void k4_residual(
    const float* __restrict__ x, float* __restrict__ out)
{
    int t  = blockIdx.x * blockDim.x + threadIdx.x;
    int i0 = t * 4;
    int b  = i0 >> 18;
    int v  = i0 & (VV - 1);
    int4 rk = *(const int4*)(g_rank + i0);

    float* ob = out + (size_t)b * CC * VV + v;
    if ((rk.x < 0) & (rk.y < 0) & (rk.z < 0) & (rk.w < 0)) {
        float4 z = make_float4(0.f, 0.f, 0.f, 0.f);
#pragma unroll
        for (int c = 0; c < CC; c++)
            *(float4*)(ob + (size_t)c * VV) = z;
        return;
    }

    const float* xb = x + (size_t)b * CC * VV + v;
#pragma unroll
    for (int c = 0; c < CC; c++) {
        const float* oc = g_o + (size_t)c * NTOT;
        float4 xv = *(const float4*)(xb + (size_t)c * VV);
        float4 ov;
        ov.x = (rk.x >= 0) ? xv.x + oc[rk.x] : 0.f;
        ov.y = (rk.y >= 0) ? xv.y + oc[rk.y] : 0.f;
        ov.z = (rk.z >= 0) ? xv.z + oc[rk.z] : 0.f;
        ov.w = (rk.w >= 0) ? xv.w + oc[rk.w] : 0.f;
        *(float4*)(ob + (size_t)c * VV) = ov;
    }
}

/* ---------------- launcher ---------------- */
extern "C" void kernel_launch(void* const* d_in, const int* in_sizes, int n_in,
                              void* d_out, int out_size)
{
    const float* x    = (const float*)d_in[0];
    const int*   mask = (const int*)  d_in[1];
    const float* w_dw = (const float*)d_in[2];
    const float* b_dw = (const float*)d_in[3];
    const float* ln_g = (const float*)d_in[4];
    const float* ln_b = (const float*)d_in[5];
    const float* w2   = (const float*)d_in[6];
    const float* b2   = (const float*)d_in[7];
    const float* w3   = (const float*)d_in[8];
    const float* b3   = (const float*)d_in[9];
    float* out = (float*)d_out;

    k0_reset<<<1, 32>>>();
    k1_rank_bits<<<(BB * VV / 4) / 256, 256>>>(mask);
    dim3 g2(128, CC, BB);
    k2_dwconv<<<g2, 128>>>(x, w_dw, b_dw);
    k3_mlp<<<NTOT / 256, 128>>>(ln_g, ln_b, w2, b2, w3, b3);
    k4_residual<<<(BB * VV / 4) / 256, 256>>>(x, out);
}